// round 14
// baseline (speedup 1.0000x reference)
#include <cuda_runtime.h>
#include <cuda_fp16.h>
#include <cstdint>

// ---------------------------------------------------------------------------
// Problem constants
// ---------------------------------------------------------------------------
#define BSZ   4096          // batch (GEMM M)
#define DK    2048          // in_features (GEMM K)
#define NCOMP 8
#define CCH   1024
#define NOUT  8192          // GEMM N

// ---------------------------------------------------------------------------
// GEMM tiling: CTA 128x256, warp tile 64x64 (2x4), BK=64, 2 stages
//   A staged as fp16 (pre-converted), B staged as raw f32 (converted in the
//   fragment path via cvt.rn.f16x2.f32)
// ---------------------------------------------------------------------------
#define BM 128
#define BN 256
#define BK 64
#define KT (DK / BK)              // 32
#define NSTAGE 2
#define LDSA_H 72                 // A: padded half stride (144B)
#define LDSB_F 72                 // B: padded float stride (288B, conflict-free LDS.64)
#define A_BYTES (BM * LDSA_H * 2)     // 18432
#define B_BYTES (BN * LDSB_F * 4)     // 73728
#define STAGE_BYTES (A_BYTES + B_BYTES)   // 92160
#define SMEM_OFF_PERM 0           // [0,512): perm slice
#define SMEM_OFF_STAGE 512
#define SMEM_BYTES (SMEM_OFF_STAGE + NSTAGE * STAGE_BYTES)   // 184832
#define GEMM_THREADS 256

#define GATE_BLOCKS 512           // 4096 warps, 1 per row

// ---------------------------------------------------------------------------
// Scratch (static device arrays; no allocations)
// ---------------------------------------------------------------------------
__device__ __align__(1024) __half d_xh[(size_t)BSZ * DK];     // 16 MB fp16 x
__device__ float d_ginv[BSZ];
__device__ int   d_gk[BSZ];
__device__ int   d_perm[BSZ];         // rows sorted by k descending
__device__ int   d_cnt_ge[NCOMP + 1]; // cnt_ge[n] = #rows with k >= n

// ---------------------------------------------------------------------------
// helpers
// ---------------------------------------------------------------------------
__device__ __forceinline__ void cpa16(void* dst_smem, const void* src_gmem) {
    uint32_t d = (uint32_t)__cvta_generic_to_shared(dst_smem);
    asm volatile("cp.async.cg.shared.global [%0], [%1], 16;\n" :: "r"(d), "l"(src_gmem));
}

__device__ __forceinline__ uint32_t f2h2(float lo, float hi) {
    uint32_t r;
    asm("cvt.rn.f16x2.f32 %0, %1, %2;" : "=r"(r) : "f"(hi), "f"(lo));
    return r;
}

// ---------------------------------------------------------------------------
// 1) gate kernel: gate + x f32->f16 + zero-fill of dead output (R10 gate part)
// ---------------------------------------------------------------------------
__global__ void gate_kernel(const float* __restrict__ x,
                            const float* __restrict__ wg,
                            const float* __restrict__ wgb,
                            float* __restrict__ out,
                            float* __restrict__ Gout) {
    int row  = (blockIdx.x * blockDim.x + threadIdx.x) >> 5;
    int lane = threadIdx.x & 31;
    const float4* xr = reinterpret_cast<const float4*>(x + (size_t)row * DK);
    const float4* wr = reinterpret_cast<const float4*>(wg);
    uint2* xo = reinterpret_cast<uint2*>(d_xh + (size_t)row * DK);
    float s = 0.f;
    #pragma unroll
    for (int j = 0; j < 4; j++) {
        float4 v[4], g[4];
        #pragma unroll
        for (int q = 0; q < 4; q++) {           // 8 independent loads (MLP)
            int c = (j * 4 + q) * 32 + lane;
            v[q] = xr[c];
            g[q] = wr[c];
        }
        #pragma unroll
        for (int q = 0; q < 4; q++) {
            int c = (j * 4 + q) * 32 + lane;
            s = fmaf(v[q].x, g[q].x, s); s = fmaf(v[q].y, g[q].y, s);
            s = fmaf(v[q].z, g[q].z, s); s = fmaf(v[q].w, g[q].w, s);
            uint2 o;
            o.x = f2h2(v[q].x, v[q].y);
            o.y = f2h2(v[q].z, v[q].w);
            xo[c] = o;
        }
    }
    #pragma unroll
    for (int o = 16; o; o >>= 1) s += __shfl_xor_sync(0xffffffffu, s, o);
    float g = 4.0f * (1.0f + tanhf(s + wgb[0]));
    int k = (int)floorf(g);
    if (k < 0) k = 0;
    if (k > NCOMP) k = NCOMP;          // k in [0, 8]
    int cnt = k + 1; if (cnt > NCOMP) cnt = NCOMP;
    float inv = 1.0f / (float)cnt;
    if (lane == 0) { d_ginv[row] = inv; d_gk[row] = k; }
    if (Gout != nullptr && lane < NCOMP)
        Gout[(size_t)row * NCOMP + lane] = (lane <= k) ? inv : 0.0f;
    // zero dead output cols [(k+1)*CCH, NOUT)
    const int zstart = (k + 1) * (CCH / 4);
    float4* p = reinterpret_cast<float4*>(out + (size_t)row * NOUT);
    const float4 z = make_float4(0.f, 0.f, 0.f, 0.f);
    for (int i = zstart + lane; i < NOUT / 4; i += 32) p[i] = z;
}

// ---------------------------------------------------------------------------
// 2) counting sort by k descending — warp-scan parallel, single CTA
// ---------------------------------------------------------------------------
#define SORT_T 256
#define PER_T (BSZ / SORT_T)   // 16
__global__ void sort_kernel() {
    __shared__ int wpart[NCOMP + 1][8];
    __shared__ int wbase[NCOMP + 1][8];
    __shared__ int tot[NCOMP + 1];
    __shared__ int sbase[NCOMP + 1];
    const int t = threadIdx.x, w = t >> 5, lane = t & 31;

    int myk[PER_T];
    int lc[NCOMP + 1];
    #pragma unroll
    for (int b = 0; b <= NCOMP; b++) lc[b] = 0;
    #pragma unroll
    for (int i = 0; i < PER_T; i++) { myk[i] = d_gk[t * PER_T + i]; lc[myk[i]]++; }

    int pre[NCOMP + 1];
    #pragma unroll
    for (int b = 0; b <= NCOMP; b++) {
        int v = lc[b], s = v;
        #pragma unroll
        for (int o = 1; o < 32; o <<= 1) {
            int u = __shfl_up_sync(0xffffffffu, s, o);
            if (lane >= o) s += u;
        }
        pre[b] = s - v;
        if (lane == 31) wpart[b][w] = s;
    }
    __syncthreads();
    if (t <= NCOMP) {
        int run = 0;
        #pragma unroll
        for (int ww = 0; ww < 8; ww++) { wbase[t][ww] = run; run += wpart[t][ww]; }
        tot[t] = run;
    }
    __syncthreads();
    if (t == 0) {
        int run = 0;
        for (int b = NCOMP; b >= 0; b--) { sbase[b] = run; run += tot[b]; d_cnt_ge[b] = run; }
    }
    __syncthreads();
    int off[NCOMP + 1];
    #pragma unroll
    for (int b = 0; b <= NCOMP; b++) off[b] = sbase[b] + wbase[b][w] + pre[b];
    #pragma unroll
    for (int i = 0; i < PER_T; i++) {
        int b = myk[i];
        d_perm[off[b]++] = t * PER_T + i;
    }
}

// ---------------------------------------------------------------------------
// 3) gathered GEMM: A fp16 from d_xh, B raw f32 from W (converted in-flight).
//    component comp uses rows perm[0 : cnt_ge[comp]]; dead tiles early-exit.
// ---------------------------------------------------------------------------
__global__ __launch_bounds__(GEMM_THREADS, 1)
void gemm_kernel(const float* __restrict__ W,
                 const float* __restrict__ bias,
                 float* __restrict__ out) {
    extern __shared__ char smemraw[];
    int*  sperm = reinterpret_cast<int*>(smemraw + SMEM_OFF_PERM);
    char* stage = smemraw + SMEM_OFF_STAGE;

    const int comp   = blockIdx.x >> 2;          // 0..7
    const int ntile  = blockIdx.x & 3;           // 0..3
    const int mtile  = blockIdx.y;                // 0..31
    const int rows   = d_cnt_ge[comp];
    if (mtile * BM >= rows) return;               // uniform early exit
    const int nvalid = min(BM, rows - mtile * BM);
    const int colBase = comp * CCH + ntile * BN;

    const int tid  = threadIdx.x;
    const int lane = tid & 31;
    const int warp = tid >> 5;
    const int wm   = warp >> 2;             // 0..1  (64 rows each)
    const int wn   = warp & 3;              // 0..3  (64 cols each)
    const int lr = lane >> 2;               // 0..7
    const int lc = lane & 3;                // 0..3

    if (tid < BM) {
        int idx = mtile * BM + min(tid, nvalid - 1);
        sperm[tid] = d_perm[idx];
    }
    __syncthreads();

    // A gather pointers: 128 rows x 8 chunks(16B), 4 per thread
    const int arow = tid >> 3;              // 0..31
    const int ach  = tid & 7;               // 16B chunk (8 halves)
    const __half* aptr[4];
    #pragma unroll
    for (int i = 0; i < 4; i++)
        aptr[i] = d_xh + (size_t)sperm[arow + i * 32] * DK + ach * 8;
    // B pointers (f32): 256 rows x 16 chunks(16B), 16 per thread
    const int brow = tid >> 4;              // 0..15
    const int bch  = tid & 15;              // 16B chunk (4 floats)
    const float* bptr[16];
    #pragma unroll
    for (int i = 0; i < 16; i++)
        bptr[i] = W + (size_t)(colBase + brow + i * 16) * DK + bch * 4;

    float c[4][8][4];
    #pragma unroll
    for (int i = 0; i < 4; i++)
        #pragma unroll
        for (int j = 0; j < 8; j++)
            #pragma unroll
            for (int r = 0; r < 4; r++) c[i][j][r] = 0.f;

    auto loadStage = [&](int s, int kt) {
        const int k0 = kt * BK;
        __half* As = reinterpret_cast<__half*>(stage + (size_t)s * STAGE_BYTES);
        float*  Bs = reinterpret_cast<float*>(stage + (size_t)s * STAGE_BYTES + A_BYTES);
        #pragma unroll
        for (int i = 0; i < 4; i++)
            cpa16(&As[(arow + i * 32) * LDSA_H + ach * 8], aptr[i] + k0);
        #pragma unroll
        for (int i = 0; i < 16; i++)
            cpa16(&Bs[(brow + i * 16) * LDSB_F + bch * 4], bptr[i] + k0);
        asm volatile("cp.async.commit_group;\n" ::);
    };

    auto computeStage = [&](int s) {
        const __half* as = reinterpret_cast<const __half*>(stage + (size_t)s * STAGE_BYTES);
        const float*  bs = reinterpret_cast<const float*>(stage + (size_t)s * STAGE_BYTES + A_BYTES);
        #pragma unroll
        for (int ks = 0; ks < BK / 16; ks++) {   // 4 steps of k16
            const int kc = ks * 16 + 2 * lc;
            uint32_t a[4][4], b[8][2];
            #pragma unroll
            for (int i = 0; i < 4; i++) {
                int r0 = wm * 64 + i * 16;
                a[i][0] = *reinterpret_cast<const uint32_t*>(&as[(r0 + lr)     * LDSA_H + kc]);
                a[i][1] = *reinterpret_cast<const uint32_t*>(&as[(r0 + lr + 8) * LDSA_H + kc]);
                a[i][2] = *reinterpret_cast<const uint32_t*>(&as[(r0 + lr)     * LDSA_H + kc + 8]);
                a[i][3] = *reinterpret_cast<const uint32_t*>(&as[(r0 + lr + 8) * LDSA_H + kc + 8]);
            }
            #pragma unroll
            for (int j = 0; j < 8; j++) {
                int n0 = wn * 64 + j * 8;
                float2 f0 = *reinterpret_cast<const float2*>(&bs[(n0 + lr) * LDSB_F + kc]);
                float2 f1 = *reinterpret_cast<const float2*>(&bs[(n0 + lr) * LDSB_F + kc + 8]);
                b[j][0] = f2h2(f0.x, f0.y);
                b[j][1] = f2h2(f1.x, f1.y);
            }
            #pragma unroll
            for (int i = 0; i < 4; i++)
                #pragma unroll
                for (int j = 0; j < 8; j++)
                    asm volatile(
                        "mma.sync.aligned.m16n8k16.row.col.f32.f16.f16.f32 "
                        "{%0,%1,%2,%3},{%4,%5,%6,%7},{%8,%9},{%0,%1,%2,%3};\n"
                        : "+f"(c[i][j][0]), "+f"(c[i][j][1]),
                          "+f"(c[i][j][2]), "+f"(c[i][j][3])
                        : "r"(a[i][0]), "r"(a[i][1]), "r"(a[i][2]), "r"(a[i][3]),
                          "r"(b[j][0]), "r"(b[j][1]));
        }
    };

    loadStage(0, 0);

    #pragma unroll 1
    for (int kt = 0; kt < KT; kt++) {
        if (kt + 1 < KT) {
            loadStage((kt + 1) & 1, kt + 1);
            asm volatile("cp.async.wait_group 1;\n" ::);
        } else {
            asm volatile("cp.async.wait_group 0;\n" ::);
        }
        __syncthreads();
        computeStage(kt & 1);
        __syncthreads();     // buffer free before it is overwritten next iter
    }

    // ---------------- epilogue: bias + per-row scale, scatter rows ----------
    #pragma unroll
    for (int i = 0; i < 4; i++) {
        #pragma unroll
        for (int h = 0; h < 2; h++) {
            const int rloc = wm * 64 + i * 16 + lr + h * 8;
            if (rloc >= nvalid) continue;
            const int gr = sperm[rloc];
            const float sc = d_ginv[gr];            // comp <= k[gr] by construction
            #pragma unroll
            for (int j = 0; j < 8; j++) {
                const int cb = colBase + wn * 64 + j * 8 + lc * 2;
                const float2 bb = *reinterpret_cast<const float2*>(&bias[cb]);
                float2 v;
                v.x = (c[i][j][2 * h + 0] + bb.x) * sc;
                v.y = (c[i][j][2 * h + 1] + bb.y) * sc;
                *reinterpret_cast<float2*>(&out[(size_t)gr * NOUT + cb]) = v;
            }
        }
    }
}

// ---------------------------------------------------------------------------
extern "C" void kernel_launch(void* const* d_in, const int* in_sizes, int n_in,
                              void* d_out, int out_size) {
    const float* x    = (const float*)d_in[0];
    const float* W    = (const float*)d_in[1];
    const float* bias = (const float*)d_in[2];
    const float* wg   = (const float*)d_in[3];
    const float* wgb  = (const float*)d_in[4];
    float* out = (float*)d_out;

    // output layout: E [BSZ*NOUT] then G [BSZ*NCOMP]
    float* Gout = nullptr;
    if ((size_t)out_size >= (size_t)BSZ * NOUT + (size_t)BSZ * NCOMP)
        Gout = out + (size_t)BSZ * NOUT;

    cudaFuncSetAttribute(gemm_kernel, cudaFuncAttributeMaxDynamicSharedMemorySize,
                         SMEM_BYTES);

    // 1) gate + x f32->f16 + dead-output zero-fill (no W pass)
    gate_kernel<<<GATE_BLOCKS, 256>>>(x, wg, wgb, out, Gout);
    // 2) sort rows by k descending
    sort_kernel<<<1, SORT_T>>>();
    // 3) gathered GEMM, B converted f32->f16 in the fragment path
    dim3 grid(NCOMP * 4, BSZ / BM);   // (comp x ntile) x mtile
    gemm_kernel<<<grid, GEMM_THREADS, SMEM_BYTES>>>(W, bias, out);
}

// round 15
// speedup vs baseline: 1.0628x; 1.0628x over previous
#include <cuda_runtime.h>
#include <cuda_fp16.h>
#include <cstdint>

// ---------------------------------------------------------------------------
// Problem constants
// ---------------------------------------------------------------------------
#define BSZ   4096          // batch (GEMM M)
#define DK    2048          // in_features (GEMM K)
#define NCOMP 8
#define CCH   1024
#define NOUT  8192          // GEMM N

// ---------------------------------------------------------------------------
// GEMM tiling: CTA 128x256, warp tile 64x64 (2x4), BK=64 halves, 4 stages
// ---------------------------------------------------------------------------
#define BM 128
#define BN 256
#define BK 64                     // k-elements per stage
#define KT (DK / BK)              // 32
#define NSTAGE 4
#define LDSD_H 72                 // padded half stride (144B, 16B-aligned)
#define A_HALFS (BM * LDSD_H)     // 9216
#define B_HALFS (BN * LDSD_H)     // 18432
#define STAGE_HALFS (A_HALFS + B_HALFS)             // 27648
#define SPERM_BYTES 512
#define SMEM_BYTES (SPERM_BYTES + NSTAGE * STAGE_HALFS * 2)   // 221696
#define GEMM_THREADS 256

// prologue kernel partition
#define GATE_BLOCKS 512                                     // 4096 warps, 1/row
#define CONV_BLOCKS (((size_t)NOUT * DK / 4) / (256 * 4))   // 4096
#define PRO_BLOCKS (GATE_BLOCKS + CONV_BLOCKS)

// ---------------------------------------------------------------------------
// Scratch (static device arrays; no allocations)
// ---------------------------------------------------------------------------
__device__ __align__(1024) __half d_xh[(size_t)BSZ * DK];     // 16 MB fp16 x
__device__ __align__(1024) __half d_wh[(size_t)NOUT * DK];    // 32 MB fp16 W
__device__ float d_ginv[BSZ];
__device__ int   d_gk[BSZ];
__device__ int   d_perm[BSZ];         // rows sorted by k descending
__device__ int   d_cnt_ge[NCOMP + 1]; // cnt_ge[n] = #rows with k >= n

// ---------------------------------------------------------------------------
// helpers
// ---------------------------------------------------------------------------
__device__ __forceinline__ void cpa16(void* dst_smem, const void* src_gmem) {
    uint32_t d = (uint32_t)__cvta_generic_to_shared(dst_smem);
    asm volatile("cp.async.cg.shared.global [%0], [%1], 16;\n" :: "r"(d), "l"(src_gmem));
}

// ---------------------------------------------------------------------------
// 1) fused prologue (R10, unchanged):
//    blocks [0, GATE_BLOCKS): gate + x f32->f16 + zero-fill of dead output
//    blocks [GATE_BLOCKS, ..): W f32->f16 (4 independent float4 per thread)
// ---------------------------------------------------------------------------
__global__ void prologue_kernel(const float* __restrict__ x,
                                const float* __restrict__ W,
                                const float* __restrict__ wg,
                                const float* __restrict__ wgb,
                                float* __restrict__ out,
                                float* __restrict__ Gout) {
    if (blockIdx.x < GATE_BLOCKS) {
        int row  = (blockIdx.x * blockDim.x + threadIdx.x) >> 5;
        int lane = threadIdx.x & 31;
        const float4* xr = reinterpret_cast<const float4*>(x + (size_t)row * DK);
        const float4* wr = reinterpret_cast<const float4*>(wg);
        uint2* xo = reinterpret_cast<uint2*>(d_xh + (size_t)row * DK);
        float s = 0.f;
        #pragma unroll
        for (int j = 0; j < 4; j++) {
            float4 v[4], g[4];
            #pragma unroll
            for (int q = 0; q < 4; q++) {           // 8 independent loads (MLP)
                int c = (j * 4 + q) * 32 + lane;
                v[q] = xr[c];
                g[q] = wr[c];
            }
            #pragma unroll
            for (int q = 0; q < 4; q++) {
                int c = (j * 4 + q) * 32 + lane;
                s = fmaf(v[q].x, g[q].x, s); s = fmaf(v[q].y, g[q].y, s);
                s = fmaf(v[q].z, g[q].z, s); s = fmaf(v[q].w, g[q].w, s);
                __half2 h0 = __floats2half2_rn(v[q].x, v[q].y);
                __half2 h1 = __floats2half2_rn(v[q].z, v[q].w);
                uint2 o;
                o.x = *reinterpret_cast<uint32_t*>(&h0);
                o.y = *reinterpret_cast<uint32_t*>(&h1);
                xo[c] = o;
            }
        }
        #pragma unroll
        for (int o = 16; o; o >>= 1) s += __shfl_xor_sync(0xffffffffu, s, o);
        float g = 4.0f * (1.0f + tanhf(s + wgb[0]));
        int k = (int)floorf(g);
        if (k < 0) k = 0;
        if (k > NCOMP) k = NCOMP;          // k in [0, 8]
        int cnt = k + 1; if (cnt > NCOMP) cnt = NCOMP;
        float inv = 1.0f / (float)cnt;
        if (lane == 0) { d_ginv[row] = inv; d_gk[row] = k; }
        if (Gout != nullptr && lane < NCOMP)
            Gout[(size_t)row * NCOMP + lane] = (lane <= k) ? inv : 0.0f;
        // zero dead output cols [(k+1)*CCH, NOUT)
        const int zstart = (k + 1) * (CCH / 4);
        float4* p = reinterpret_cast<float4*>(out + (size_t)row * NOUT);
        const float4 z = make_float4(0.f, 0.f, 0.f, 0.f);
        for (int i = zstart + lane; i < NOUT / 4; i += 32) p[i] = z;
    } else {
        size_t base = ((size_t)(blockIdx.x - GATE_BLOCKS) * 4) * blockDim.x
                      + threadIdx.x;
        const float4* W4 = reinterpret_cast<const float4*>(W);
        uint2* O2 = reinterpret_cast<uint2*>(d_wh);
        float4 v[4];
        #pragma unroll
        for (int q = 0; q < 4; q++) v[q] = W4[base + (size_t)q * blockDim.x];
        #pragma unroll
        for (int q = 0; q < 4; q++) {
            __half2 h0 = __floats2half2_rn(v[q].x, v[q].y);
            __half2 h1 = __floats2half2_rn(v[q].z, v[q].w);
            uint2 o;
            o.x = *reinterpret_cast<uint32_t*>(&h0);
            o.y = *reinterpret_cast<uint32_t*>(&h1);
            O2[base + (size_t)q * blockDim.x] = o;
        }
    }
}

// ---------------------------------------------------------------------------
// 2) counting sort by k descending — warp-scan parallel, single CTA
// ---------------------------------------------------------------------------
#define SORT_T 256
#define PER_T (BSZ / SORT_T)   // 16
__global__ void sort_kernel() {
    __shared__ int wpart[NCOMP + 1][8];
    __shared__ int wbase[NCOMP + 1][8];
    __shared__ int tot[NCOMP + 1];
    __shared__ int sbase[NCOMP + 1];
    const int t = threadIdx.x, w = t >> 5, lane = t & 31;

    int myk[PER_T];
    int lc[NCOMP + 1];
    #pragma unroll
    for (int b = 0; b <= NCOMP; b++) lc[b] = 0;
    #pragma unroll
    for (int i = 0; i < PER_T; i++) { myk[i] = d_gk[t * PER_T + i]; lc[myk[i]]++; }

    int pre[NCOMP + 1];
    #pragma unroll
    for (int b = 0; b <= NCOMP; b++) {
        int v = lc[b], s = v;
        #pragma unroll
        for (int o = 1; o < 32; o <<= 1) {
            int u = __shfl_up_sync(0xffffffffu, s, o);
            if (lane >= o) s += u;
        }
        pre[b] = s - v;
        if (lane == 31) wpart[b][w] = s;
    }
    __syncthreads();
    if (t <= NCOMP) {
        int run = 0;
        #pragma unroll
        for (int ww = 0; ww < 8; ww++) { wbase[t][ww] = run; run += wpart[t][ww]; }
        tot[t] = run;
    }
    __syncthreads();
    if (t == 0) {
        int run = 0;
        for (int b = NCOMP; b >= 0; b--) { sbase[b] = run; run += tot[b]; d_cnt_ge[b] = run; }
    }
    __syncthreads();
    int off[NCOMP + 1];
    #pragma unroll
    for (int b = 0; b <= NCOMP; b++) off[b] = sbase[b] + wbase[b][w] + pre[b];
    #pragma unroll
    for (int i = 0; i < PER_T; i++) {
        int b = myk[i];
        d_perm[off[b]++] = t * PER_T + i;
    }
}

// ---------------------------------------------------------------------------
// 3) gathered fp16 GEMM: component comp uses rows perm[0 : cnt_ge[comp]];
//    dead tiles early-exit (zeros written by prologue). 4-stage pipeline.
// ---------------------------------------------------------------------------
__global__ __launch_bounds__(GEMM_THREADS, 1)
void gemm_kernel(const float* __restrict__ bias, float* __restrict__ out) {
    extern __shared__ char smemraw[];
    int*    sperm = reinterpret_cast<int*>(smemraw);
    __half* smem  = reinterpret_cast<__half*>(smemraw + SPERM_BYTES);

    const int comp   = blockIdx.x >> 2;          // 0..7
    const int ntile  = blockIdx.x & 3;           // 0..3
    const int mtile  = blockIdx.y;                // 0..31
    const int rows   = d_cnt_ge[comp];
    if (mtile * BM >= rows) return;               // uniform early exit
    const int nvalid = min(BM, rows - mtile * BM);
    const int colBase = comp * CCH + ntile * BN;

    const int tid  = threadIdx.x;
    const int lane = tid & 31;
    const int warp = tid >> 5;
    const int wm   = warp >> 2;             // 0..1  (64 rows each)
    const int wn   = warp & 3;              // 0..3  (64 cols each)
    const int lr = lane >> 2;               // 0..7
    const int lc = lane & 3;                // 0..3

    if (tid < BM) {
        int idx = mtile * BM + min(tid, nvalid - 1);
        sperm[tid] = d_perm[idx];
    }
    __syncthreads();

    // gathered source pointers (fixed rows across k-tiles)
    const int arow = tid >> 3;              // 0..31
    const int ach  = tid & 7;               // 16B chunk (8 halves)
    const __half* aptr[4];
    #pragma unroll
    for (int i = 0; i < 4; i++)
        aptr[i] = d_xh + (size_t)sperm[arow + i * 32] * DK + ach * 8;
    const __half* bptr[8];
    #pragma unroll
    for (int i = 0; i < 8; i++)
        bptr[i] = d_wh + (size_t)(colBase + arow + i * 32) * DK + ach * 8;

    float c[4][8][4];
    #pragma unroll
    for (int i = 0; i < 4; i++)
        #pragma unroll
        for (int j = 0; j < 8; j++)
            #pragma unroll
            for (int r = 0; r < 4; r++) c[i][j][r] = 0.f;

    auto loadStage = [&](int s, int kt) {
        const int k0 = kt * BK;
        __half* As = smem + (size_t)s * STAGE_HALFS;
        __half* Bs = As + A_HALFS;
        #pragma unroll
        for (int i = 0; i < 4; i++)
            cpa16(&As[(arow + i * 32) * LDSD_H + ach * 8], aptr[i] + k0);
        #pragma unroll
        for (int i = 0; i < 8; i++)
            cpa16(&Bs[(arow + i * 32) * LDSD_H + ach * 8], bptr[i] + k0);
        asm volatile("cp.async.commit_group;\n" ::);
    };

    auto computeStage = [&](int s) {
        const __half* as = smem + (size_t)s * STAGE_HALFS;
        const __half* bs = as + A_HALFS;
        #pragma unroll
        for (int ks = 0; ks < BK / 16; ks++) {   // 4 steps of k16
            const int kc = ks * 16 + 2 * lc;
            uint32_t a[4][4], b[8][2];
            #pragma unroll
            for (int i = 0; i < 4; i++) {
                int r0 = wm * 64 + i * 16;
                a[i][0] = *reinterpret_cast<const uint32_t*>(&as[(r0 + lr)     * LDSD_H + kc]);
                a[i][1] = *reinterpret_cast<const uint32_t*>(&as[(r0 + lr + 8) * LDSD_H + kc]);
                a[i][2] = *reinterpret_cast<const uint32_t*>(&as[(r0 + lr)     * LDSD_H + kc + 8]);
                a[i][3] = *reinterpret_cast<const uint32_t*>(&as[(r0 + lr + 8) * LDSD_H + kc + 8]);
            }
            #pragma unroll
            for (int j = 0; j < 8; j++) {
                int n0 = wn * 64 + j * 8;
                b[j][0] = *reinterpret_cast<const uint32_t*>(&bs[(n0 + lr) * LDSD_H + kc]);
                b[j][1] = *reinterpret_cast<const uint32_t*>(&bs[(n0 + lr) * LDSD_H + kc + 8]);
            }
            #pragma unroll
            for (int i = 0; i < 4; i++)
                #pragma unroll
                for (int j = 0; j < 8; j++)
                    asm volatile(
                        "mma.sync.aligned.m16n8k16.row.col.f32.f16.f16.f32 "
                        "{%0,%1,%2,%3},{%4,%5,%6,%7},{%8,%9},{%0,%1,%2,%3};\n"
                        : "+f"(c[i][j][0]), "+f"(c[i][j][1]),
                          "+f"(c[i][j][2]), "+f"(c[i][j][3])
                        : "r"(a[i][0]), "r"(a[i][1]), "r"(a[i][2]), "r"(a[i][3]),
                          "r"(b[j][0]), "r"(b[j][1]));
        }
    };

    // prefetch stages 0..NSTAGE-2
    loadStage(0, 0);
    loadStage(1, 1);
    loadStage(2, 2);

    #pragma unroll 1
    for (int kt = 0; kt < KT; kt++) {
        // sound wait: allow exactly the number of still-pending newer groups
        if (kt + 3 <= KT - 1)      asm volatile("cp.async.wait_group 2;\n" ::);
        else if (kt + 2 <= KT - 1) asm volatile("cp.async.wait_group 1;\n" ::);
        else if (kt + 1 <= KT - 1) asm volatile("cp.async.wait_group 1;\n" ::);
        else                       asm volatile("cp.async.wait_group 0;\n" ::);
        __syncthreads();
        if (kt + NSTAGE - 1 < KT)
            loadStage((kt + NSTAGE - 1) % NSTAGE, kt + NSTAGE - 1);
        computeStage(kt % NSTAGE);
    }

    // ---------------- epilogue: bias + per-row scale, scatter rows ----------
    #pragma unroll
    for (int i = 0; i < 4; i++) {
        #pragma unroll
        for (int h = 0; h < 2; h++) {
            const int rloc = wm * 64 + i * 16 + lr + h * 8;
            if (rloc >= nvalid) continue;
            const int gr = sperm[rloc];
            const float sc = d_ginv[gr];            // comp <= k[gr] by construction
            #pragma unroll
            for (int j = 0; j < 8; j++) {
                const int cb = colBase + wn * 64 + j * 8 + lc * 2;
                const float2 bb = *reinterpret_cast<const float2*>(&bias[cb]);
                float2 v;
                v.x = (c[i][j][2 * h + 0] + bb.x) * sc;
                v.y = (c[i][j][2 * h + 1] + bb.y) * sc;
                *reinterpret_cast<float2*>(&out[(size_t)gr * NOUT + cb]) = v;
            }
        }
    }
}

// ---------------------------------------------------------------------------
extern "C" void kernel_launch(void* const* d_in, const int* in_sizes, int n_in,
                              void* d_out, int out_size) {
    const float* x    = (const float*)d_in[0];
    const float* W    = (const float*)d_in[1];
    const float* bias = (const float*)d_in[2];
    const float* wg   = (const float*)d_in[3];
    const float* wgb  = (const float*)d_in[4];
    float* out = (float*)d_out;

    // output layout: E [BSZ*NOUT] then G [BSZ*NCOMP]
    float* Gout = nullptr;
    if ((size_t)out_size >= (size_t)BSZ * NOUT + (size_t)BSZ * NCOMP)
        Gout = out + (size_t)BSZ * NOUT;

    cudaFuncSetAttribute(gemm_kernel, cudaFuncAttributeMaxDynamicSharedMemorySize,
                         SMEM_BYTES);

    // 1) fused gate(+x conv, +zfill) + W conv  (high-MLP version)
    prologue_kernel<<<(unsigned)PRO_BLOCKS, 256>>>(x, W, wg, wgb, out, Gout);
    // 2) sort rows by k descending
    sort_kernel<<<1, SORT_T>>>();
    // 3) gathered fp16 GEMM over live pairs (early exit on dead tiles)
    dim3 grid(NCOMP * 4, BSZ / BM);   // (comp x ntile) x mtile
    gemm_kernel<<<grid, GEMM_THREADS, SMEM_BYTES>>>(bias, out);
}

// round 16
// speedup vs baseline: 1.0656x; 1.0027x over previous
#include <cuda_runtime.h>
#include <cuda_fp16.h>
#include <cstdint>

// ---------------------------------------------------------------------------
// Problem constants
// ---------------------------------------------------------------------------
#define BSZ   4096          // batch (GEMM M)
#define DK    2048          // in_features (GEMM K)
#define NCOMP 8
#define CCH   1024
#define NOUT  8192          // GEMM N

// ---------------------------------------------------------------------------
// GEMM tiling: CTA 128x256, warp tile 64x64 (2x4), BK=64 halves, 4 stages
// ---------------------------------------------------------------------------
#define BM 128
#define BN 256
#define BK 64                     // k-elements per stage
#define KT (DK / BK)              // 32
#define NSTAGE 4
#define LDSD_H 72                 // padded half stride (144B, 16B-aligned)
#define A_HALFS (BM * LDSD_H)     // 9216
#define B_HALFS (BN * LDSD_H)     // 18432
#define STAGE_HALFS (A_HALFS + B_HALFS)             // 27648
#define SPERM_BYTES 512
#define SMEM_BYTES (SPERM_BYTES + NSTAGE * STAGE_HALFS * 2)   // 221696
#define GEMM_THREADS 256

// prologue kernel partition
#define GATE_BLOCKS 512                                     // 4096 warps, 1/row
#define CONV_BLOCKS (((size_t)NOUT * DK / 4) / (256 * 8))   // 2048 (8 float4/thr)
#define PRO_BLOCKS (GATE_BLOCKS + CONV_BLOCKS)

// ---------------------------------------------------------------------------
// Scratch (static device arrays; no allocations)
// ---------------------------------------------------------------------------
__device__ __align__(1024) __half d_xh[(size_t)BSZ * DK];     // 16 MB fp16 x
__device__ __align__(1024) __half d_wh[(size_t)NOUT * DK];    // 32 MB fp16 W
__device__ float d_ginv[BSZ];
__device__ int   d_gk[BSZ];
__device__ int   d_perm[BSZ];         // rows sorted by k descending
__device__ int   d_cnt_ge[NCOMP + 1]; // cnt_ge[n] = #rows with k >= n

// ---------------------------------------------------------------------------
// helpers
// ---------------------------------------------------------------------------
__device__ __forceinline__ void cpa16(void* dst_smem, const void* src_gmem) {
    uint32_t d = (uint32_t)__cvta_generic_to_shared(dst_smem);
    asm volatile("cp.async.cg.shared.global [%0], [%1], 16;\n" :: "r"(d), "l"(src_gmem));
}

// ---------------------------------------------------------------------------
// 1) fused prologue:
//    blocks [0, GATE_BLOCKS): gate + x f32->f16 + zero-fill of dead output
//    blocks [GATE_BLOCKS, ..): W f32->f16 (8 independent float4 per thread)
// ---------------------------------------------------------------------------
__global__ void prologue_kernel(const float* __restrict__ x,
                                const float* __restrict__ W,
                                const float* __restrict__ wg,
                                const float* __restrict__ wgb,
                                float* __restrict__ out,
                                float* __restrict__ Gout) {
    if (blockIdx.x < GATE_BLOCKS) {
        int row  = (blockIdx.x * blockDim.x + threadIdx.x) >> 5;
        int lane = threadIdx.x & 31;
        const float4* xr = reinterpret_cast<const float4*>(x + (size_t)row * DK);
        const float4* wr = reinterpret_cast<const float4*>(wg);
        uint2* xo = reinterpret_cast<uint2*>(d_xh + (size_t)row * DK);
        float s = 0.f;
        #pragma unroll
        for (int j = 0; j < 4; j++) {
            float4 v[4], g[4];
            #pragma unroll
            for (int q = 0; q < 4; q++) {           // 8 independent loads (MLP)
                int c = (j * 4 + q) * 32 + lane;
                v[q] = xr[c];
                g[q] = wr[c];
            }
            #pragma unroll
            for (int q = 0; q < 4; q++) {
                int c = (j * 4 + q) * 32 + lane;
                s = fmaf(v[q].x, g[q].x, s); s = fmaf(v[q].y, g[q].y, s);
                s = fmaf(v[q].z, g[q].z, s); s = fmaf(v[q].w, g[q].w, s);
                __half2 h0 = __floats2half2_rn(v[q].x, v[q].y);
                __half2 h1 = __floats2half2_rn(v[q].z, v[q].w);
                uint2 o;
                o.x = *reinterpret_cast<uint32_t*>(&h0);
                o.y = *reinterpret_cast<uint32_t*>(&h1);
                xo[c] = o;
            }
        }
        #pragma unroll
        for (int o = 16; o; o >>= 1) s += __shfl_xor_sync(0xffffffffu, s, o);
        float g = 4.0f * (1.0f + tanhf(s + wgb[0]));
        int k = (int)floorf(g);
        if (k < 0) k = 0;
        if (k > NCOMP) k = NCOMP;          // k in [0, 8]
        int cnt = k + 1; if (cnt > NCOMP) cnt = NCOMP;
        float inv = 1.0f / (float)cnt;
        if (lane == 0) { d_ginv[row] = inv; d_gk[row] = k; }
        if (Gout != nullptr && lane < NCOMP)
            Gout[(size_t)row * NCOMP + lane] = (lane <= k) ? inv : 0.0f;
        // zero dead output cols [(k+1)*CCH, NOUT)
        const int zstart = (k + 1) * (CCH / 4);
        float4* p = reinterpret_cast<float4*>(out + (size_t)row * NOUT);
        const float4 z = make_float4(0.f, 0.f, 0.f, 0.f);
        for (int i = zstart + lane; i < NOUT / 4; i += 32) p[i] = z;
    } else {
        // ----- W conversion: f32 -> f16 (rn), 8 independent float4/thread ---
        size_t base = ((size_t)(blockIdx.x - GATE_BLOCKS) * 8) * blockDim.x
                      + threadIdx.x;
        const float4* W4 = reinterpret_cast<const float4*>(W);
        uint2* O2 = reinterpret_cast<uint2*>(d_wh);
        float4 v[8];
        #pragma unroll
        for (int q = 0; q < 8; q++) v[q] = W4[base + (size_t)q * blockDim.x];
        #pragma unroll
        for (int q = 0; q < 8; q++) {
            __half2 h0 = __floats2half2_rn(v[q].x, v[q].y);
            __half2 h1 = __floats2half2_rn(v[q].z, v[q].w);
            uint2 o;
            o.x = *reinterpret_cast<uint32_t*>(&h0);
            o.y = *reinterpret_cast<uint32_t*>(&h1);
            O2[base + (size_t)q * blockDim.x] = o;
        }
    }
}

// ---------------------------------------------------------------------------
// 2) counting sort by k descending — warp-scan parallel, single CTA
// ---------------------------------------------------------------------------
#define SORT_T 256
#define PER_T (BSZ / SORT_T)   // 16
__global__ void sort_kernel() {
    __shared__ int wpart[NCOMP + 1][8];
    __shared__ int wbase[NCOMP + 1][8];
    __shared__ int tot[NCOMP + 1];
    __shared__ int sbase[NCOMP + 1];
    const int t = threadIdx.x, w = t >> 5, lane = t & 31;

    int myk[PER_T];
    int lc[NCOMP + 1];
    #pragma unroll
    for (int b = 0; b <= NCOMP; b++) lc[b] = 0;
    #pragma unroll
    for (int i = 0; i < PER_T; i++) { myk[i] = d_gk[t * PER_T + i]; lc[myk[i]]++; }

    int pre[NCOMP + 1];
    #pragma unroll
    for (int b = 0; b <= NCOMP; b++) {
        int v = lc[b], s = v;
        #pragma unroll
        for (int o = 1; o < 32; o <<= 1) {
            int u = __shfl_up_sync(0xffffffffu, s, o);
            if (lane >= o) s += u;
        }
        pre[b] = s - v;
        if (lane == 31) wpart[b][w] = s;
    }
    __syncthreads();
    if (t <= NCOMP) {
        int run = 0;
        #pragma unroll
        for (int ww = 0; ww < 8; ww++) { wbase[t][ww] = run; run += wpart[t][ww]; }
        tot[t] = run;
    }
    __syncthreads();
    if (t == 0) {
        int run = 0;
        for (int b = NCOMP; b >= 0; b--) { sbase[b] = run; run += tot[b]; d_cnt_ge[b] = run; }
    }
    __syncthreads();
    int off[NCOMP + 1];
    #pragma unroll
    for (int b = 0; b <= NCOMP; b++) off[b] = sbase[b] + wbase[b][w] + pre[b];
    #pragma unroll
    for (int i = 0; i < PER_T; i++) {
        int b = myk[i];
        d_perm[off[b]++] = t * PER_T + i;
    }
}

// ---------------------------------------------------------------------------
// 3) gathered fp16 GEMM (R15, unchanged): comp uses rows perm[0:cnt_ge[comp]];
//    dead tiles early-exit (zeros written by prologue). 4-stage pipeline.
// ---------------------------------------------------------------------------
__global__ __launch_bounds__(GEMM_THREADS, 1)
void gemm_kernel(const float* __restrict__ bias, float* __restrict__ out) {
    extern __shared__ char smemraw[];
    int*    sperm = reinterpret_cast<int*>(smemraw);
    __half* smem  = reinterpret_cast<__half*>(smemraw + SPERM_BYTES);

    const int comp   = blockIdx.x >> 2;          // 0..7
    const int ntile  = blockIdx.x & 3;           // 0..3
    const int mtile  = blockIdx.y;                // 0..31
    const int rows   = d_cnt_ge[comp];
    if (mtile * BM >= rows) return;               // uniform early exit
    const int nvalid = min(BM, rows - mtile * BM);
    const int colBase = comp * CCH + ntile * BN;

    const int tid  = threadIdx.x;
    const int lane = tid & 31;
    const int warp = tid >> 5;
    const int wm   = warp >> 2;             // 0..1  (64 rows each)
    const int wn   = warp & 3;              // 0..3  (64 cols each)
    const int lr = lane >> 2;               // 0..7
    const int lc = lane & 3;                // 0..3

    if (tid < BM) {
        int idx = mtile * BM + min(tid, nvalid - 1);
        sperm[tid] = d_perm[idx];
    }
    __syncthreads();

    // gathered source pointers (fixed rows across k-tiles)
    const int arow = tid >> 3;              // 0..31
    const int ach  = tid & 7;               // 16B chunk (8 halves)
    const __half* aptr[4];
    #pragma unroll
    for (int i = 0; i < 4; i++)
        aptr[i] = d_xh + (size_t)sperm[arow + i * 32] * DK + ach * 8;
    const __half* bptr[8];
    #pragma unroll
    for (int i = 0; i < 8; i++)
        bptr[i] = d_wh + (size_t)(colBase + arow + i * 32) * DK + ach * 8;

    float c[4][8][4];
    #pragma unroll
    for (int i = 0; i < 4; i++)
        #pragma unroll
        for (int j = 0; j < 8; j++)
            #pragma unroll
            for (int r = 0; r < 4; r++) c[i][j][r] = 0.f;

    auto loadStage = [&](int s, int kt) {
        const int k0 = kt * BK;
        __half* As = smem + (size_t)s * STAGE_HALFS;
        __half* Bs = As + A_HALFS;
        #pragma unroll
        for (int i = 0; i < 4; i++)
            cpa16(&As[(arow + i * 32) * LDSD_H + ach * 8], aptr[i] + k0);
        #pragma unroll
        for (int i = 0; i < 8; i++)
            cpa16(&Bs[(arow + i * 32) * LDSD_H + ach * 8], bptr[i] + k0);
        asm volatile("cp.async.commit_group;\n" ::);
    };

    auto computeStage = [&](int s) {
        const __half* as = smem + (size_t)s * STAGE_HALFS;
        const __half* bs = as + A_HALFS;
        #pragma unroll
        for (int ks = 0; ks < BK / 16; ks++) {   // 4 steps of k16
            const int kc = ks * 16 + 2 * lc;
            uint32_t a[4][4], b[8][2];
            #pragma unroll
            for (int i = 0; i < 4; i++) {
                int r0 = wm * 64 + i * 16;
                a[i][0] = *reinterpret_cast<const uint32_t*>(&as[(r0 + lr)     * LDSD_H + kc]);
                a[i][1] = *reinterpret_cast<const uint32_t*>(&as[(r0 + lr + 8) * LDSD_H + kc]);
                a[i][2] = *reinterpret_cast<const uint32_t*>(&as[(r0 + lr)     * LDSD_H + kc + 8]);
                a[i][3] = *reinterpret_cast<const uint32_t*>(&as[(r0 + lr + 8) * LDSD_H + kc + 8]);
            }
            #pragma unroll
            for (int j = 0; j < 8; j++) {
                int n0 = wn * 64 + j * 8;
                b[j][0] = *reinterpret_cast<const uint32_t*>(&bs[(n0 + lr) * LDSD_H + kc]);
                b[j][1] = *reinterpret_cast<const uint32_t*>(&bs[(n0 + lr) * LDSD_H + kc + 8]);
            }
            #pragma unroll
            for (int i = 0; i < 4; i++)
                #pragma unroll
                for (int j = 0; j < 8; j++)
                    asm volatile(
                        "mma.sync.aligned.m16n8k16.row.col.f32.f16.f16.f32 "
                        "{%0,%1,%2,%3},{%4,%5,%6,%7},{%8,%9},{%0,%1,%2,%3};\n"
                        : "+f"(c[i][j][0]), "+f"(c[i][j][1]),
                          "+f"(c[i][j][2]), "+f"(c[i][j][3])
                        : "r"(a[i][0]), "r"(a[i][1]), "r"(a[i][2]), "r"(a[i][3]),
                          "r"(b[j][0]), "r"(b[j][1]));
        }
    };

    // prefetch stages 0..NSTAGE-2
    loadStage(0, 0);
    loadStage(1, 1);
    loadStage(2, 2);

    #pragma unroll 1
    for (int kt = 0; kt < KT; kt++) {
        // sound wait: allow exactly the number of still-pending newer groups
        if (kt + 3 <= KT - 1)      asm volatile("cp.async.wait_group 2;\n" ::);
        else if (kt + 1 <= KT - 1) asm volatile("cp.async.wait_group 1;\n" ::);
        else                       asm volatile("cp.async.wait_group 0;\n" ::);
        __syncthreads();
        if (kt + NSTAGE - 1 < KT)
            loadStage((kt + NSTAGE - 1) % NSTAGE, kt + NSTAGE - 1);
        computeStage(kt % NSTAGE);
    }

    // ---------------- epilogue: bias + per-row scale, scatter rows ----------
    #pragma unroll
    for (int i = 0; i < 4; i++) {
        #pragma unroll
        for (int h = 0; h < 2; h++) {
            const int rloc = wm * 64 + i * 16 + lr + h * 8;
            if (rloc >= nvalid) continue;
            const int gr = sperm[rloc];
            const float sc = d_ginv[gr];            // comp <= k[gr] by construction
            #pragma unroll
            for (int j = 0; j < 8; j++) {
                const int cb = colBase + wn * 64 + j * 8 + lc * 2;
                const float2 bb = *reinterpret_cast<const float2*>(&bias[cb]);
                float2 v;
                v.x = (c[i][j][2 * h + 0] + bb.x) * sc;
                v.y = (c[i][j][2 * h + 1] + bb.y) * sc;
                *reinterpret_cast<float2*>(&out[(size_t)gr * NOUT + cb]) = v;
            }
        }
    }
}

// ---------------------------------------------------------------------------
extern "C" void kernel_launch(void* const* d_in, const int* in_sizes, int n_in,
                              void* d_out, int out_size) {
    const float* x    = (const float*)d_in[0];
    const float* W    = (const float*)d_in[1];
    const float* bias = (const float*)d_in[2];
    const float* wg   = (const float*)d_in[3];
    const float* wgb  = (const float*)d_in[4];
    float* out = (float*)d_out;

    // output layout: E [BSZ*NOUT] then G [BSZ*NCOMP]
    float* Gout = nullptr;
    if ((size_t)out_size >= (size_t)BSZ * NOUT + (size_t)BSZ * NCOMP)
        Gout = out + (size_t)BSZ * NOUT;

    cudaFuncSetAttribute(gemm_kernel, cudaFuncAttributeMaxDynamicSharedMemorySize,
                         SMEM_BYTES);

    // 1) fused gate(+x conv, +zfill) + W conv  (MLP-8 both sections)
    prologue_kernel<<<(unsigned)PRO_BLOCKS, 256>>>(x, W, wg, wgb, out, Gout);
    // 2) sort rows by k descending
    sort_kernel<<<1, SORT_T>>>();
    // 3) gathered fp16 GEMM over live pairs (early exit on dead tiles)
    dim3 grid(NCOMP * 4, BSZ / BM);   // (comp x ntile) x mtile
    gemm_kernel<<<grid, GEMM_THREADS, SMEM_BYTES>>>(bias, out);
}